// round 3
// baseline (speedup 1.0000x reference)
#include <cuda_runtime.h>
#include <math.h>

#define NN 320
#define HN 160
#define NPIX (NN*NN)
#define NVEC (4*NPIX)        // 409600 complex
#define NIMG 64              // 4 shots * 16 coils
#define RHO_F 0.1f
#define EPS_F 1e-12f

// ---------------- device globals (scratch) ----------------
__device__ float2 d_scr[NIMG*NPIX];   // 52.4 MB k-space / hybrid scratch
__device__ float2 d_x[NVEC];
__device__ float2 d_r[NVEC];
__device__ float2 d_p[NVEC];
__device__ float2 d_Ap[NVEC];
__device__ float2 d_W[NN];            // twiddle table exp(-2*pi*i*k/320)
__device__ float  d_partP[1280];      // pAp partials (and init |r|^2 goes to d_pr0)
__device__ float  d_pr0[1600];        // |r|^2 partials, double-buffered
__device__ float  d_pr1[1600];

// ---------------- complex helpers ----------------
__device__ __forceinline__ float2 cad(float2 a, float2 b){ return make_float2(a.x+b.x, a.y+b.y); }
__device__ __forceinline__ float2 csb(float2 a, float2 b){ return make_float2(a.x-b.x, a.y-b.y); }
__device__ __forceinline__ float2 cml(float2 a, float2 b){
    return make_float2(fmaf(a.x,b.x,-a.y*b.y), fmaf(a.x,b.y, a.y*b.x));
}
__device__ __forceinline__ float2 cmlcj(float2 a, float2 b){ // a * conj(b)
    return make_float2(fmaf(a.x,b.x, a.y*b.y), fmaf(a.y,b.x,-a.x*b.y));
}

template<int DIR>
__device__ __forceinline__ float2 tw(const float2* W, int idx){
    float2 w = W[idx];
    return (DIR > 0) ? w : make_float2(w.x, -w.y);
}

// ---------------- Stockham radix-4 stage ----------------
template<int SS, int MM, int DIR>
__device__ __forceinline__ void stage_r4(const float2* src, float2* dst, const float2* W, int u){
    int p = u / SS;
    int q = u - p * SS;
    float2 a0 = src[q + SS*p];
    float2 a1 = src[q + SS*(p + MM)];
    float2 a2 = src[q + SS*(p + 2*MM)];
    float2 a3 = src[q + SS*(p + 3*MM)];
    float2 t0 = cad(a0,a2), t1 = csb(a0,a2), t2 = cad(a1,a3), t3 = csb(a1,a3);
    float2 b0 = cad(t0,t2), b2 = csb(t0,t2);
    float2 b1, b3;
    if (DIR > 0){
        b1 = make_float2(t1.x + t3.y, t1.y - t3.x);
        b3 = make_float2(t1.x - t3.y, t1.y + t3.x);
    } else {
        b1 = make_float2(t1.x - t3.y, t1.y + t3.x);
        b3 = make_float2(t1.x + t3.y, t1.y - t3.x);
    }
    int base = q + SS*4*p;
    dst[base]        = b0;
    dst[base +   SS] = cml(b1, tw<DIR>(W,     SS*p));
    dst[base + 2*SS] = cml(b2, tw<DIR>(W, 2 * SS*p));
    dst[base + 3*SS] = cml(b3, tw<DIR>(W, 3 * SS*p));
}

// ---------------- 320-point FFT, 80 threads (u in [0,80)) ----------------
template<int DIR>
__device__ __forceinline__ void fft320(float2* A, float2* B, const float2* W, int u){
    if (u < 64){
        float2 a0=A[u], a1=A[u+64], a2=A[u+128], a3=A[u+192], a4=A[u+256];
        const float C1 =  0.3090169943749474241f;
        const float C2 = -0.8090169943749474241f;
        const float S1 =  0.9510565162951535721f;
        const float S2 =  0.5877852522924731292f;
        float2 t1 = cad(a1,a4), t2 = cad(a2,a3), t3 = csb(a1,a4), t4 = csb(a2,a3);
        float2 b0 = make_float2(a0.x + t1.x + t2.x, a0.y + t1.y + t2.y);
        float2 m1 = make_float2(fmaf(C1,t1.x, fmaf(C2,t2.x, a0.x)),
                                fmaf(C1,t1.y, fmaf(C2,t2.y, a0.y)));
        float2 m2 = make_float2(fmaf(C2,t1.x, fmaf(C1,t2.x, a0.x)),
                                fmaf(C2,t1.y, fmaf(C1,t2.y, a0.y)));
        float2 w1 = make_float2(fmaf(S1,t3.x,  S2*t4.x), fmaf(S1,t3.y,  S2*t4.y));
        float2 w2 = make_float2(fmaf(S2,t3.x, -S1*t4.x), fmaf(S2,t3.y, -S1*t4.y));
        float2 b1,b2,b3,b4;
        if (DIR > 0){
            b1 = make_float2(m1.x + w1.y, m1.y - w1.x);
            b4 = make_float2(m1.x - w1.y, m1.y + w1.x);
            b2 = make_float2(m2.x + w2.y, m2.y - w2.x);
            b3 = make_float2(m2.x - w2.y, m2.y + w2.x);
        } else {
            b1 = make_float2(m1.x - w1.y, m1.y + w1.x);
            b4 = make_float2(m1.x + w1.y, m1.y - w1.x);
            b2 = make_float2(m2.x - w2.y, m2.y + w2.x);
            b3 = make_float2(m2.x + w2.y, m2.y - w2.x);
        }
        B[5*u]   = b0;
        B[5*u+1] = cml(b1, tw<DIR>(W,   u));
        B[5*u+2] = cml(b2, tw<DIR>(W, 2*u));
        B[5*u+3] = cml(b3, tw<DIR>(W, 3*u));
        B[5*u+4] = cml(b4, tw<DIR>(W, 4*u));
    }
    __syncthreads();
    stage_r4<5,16,DIR>(B, A, W, u);  __syncthreads();
    stage_r4<20,4,DIR>(A, B, W, u);  __syncthreads();
    stage_r4<80,1,DIR>(B, A, W, u);  __syncthreads();
}

// ---------------- 320-thread block reduce -> part[bid] ----------------
__device__ __forceinline__ void reduce320(float v, float* part){
    __shared__ float rb[10];
    int tid = threadIdx.x;
    #pragma unroll
    for (int o = 16; o > 0; o >>= 1) v += __shfl_down_sync(0xffffffffu, v, o);
    if ((tid & 31) == 0) rb[tid >> 5] = v;
    __syncthreads();
    if (tid == 0){
        float t = 0.f;
        #pragma unroll
        for (int i = 0; i < 10; i++) t += rb[i];
        part[blockIdx.x] = t;
    }
}

// ---------------- in-block deterministic sum of a partial array, broadcast ----------------
// blockDim 256 assumed. Returns the same value to all threads.
__device__ __forceinline__ float block_sum_arr(const float* __restrict__ a, int n){
    __shared__ float rb[8];
    __shared__ float bc;
    int tid = threadIdx.x;
    float v = 0.f;
    for (int i = tid; i < n; i += 256) v += a[i];
    #pragma unroll
    for (int o = 16; o > 0; o >>= 1) v += __shfl_down_sync(0xffffffffu, v, o);
    if ((tid & 31) == 0) rb[tid >> 5] = v;
    __syncthreads();
    if (tid == 0){
        float t = 0.f;
        #pragma unroll
        for (int k = 0; k < 8; k++) t += rb[k];
        bc = t;
    }
    __syncthreads();
    return bc;
}

// ---------------- init: twiddles ----------------
__global__ void k_init_tw(){
    int k = threadIdx.x;
    double a = -2.0 * 3.14159265358979323846 * (double)k / 320.0;
    d_W[k] = make_float2((float)cos(a), (float)sin(a));
}

// ---------------- K1: forward row FFT of csm*p, ishift folded ----------------
__global__ void __launch_bounds__(320) k_fwd_row(const float2* __restrict__ csm,
                                                 const float2* __restrict__ pin){
    __shared__ float2 Ash[4][321], Bsh[4][321], Wsh[NN];
    int tid = threadIdx.x, lane = tid / 80, u = tid % 80;
    Wsh[tid] = d_W[tid];
    int bid = blockIdx.x;
    int g  = bid / 80;            // s*16 + c
    int h0 = (bid % 80) * 4;
    int s = g >> 4, c = g & 15;
    int wi = tid + HN; if (wi >= NN) wi -= NN;
    #pragma unroll
    for (int k = 0; k < 4; k++){
        int h = h0 + k;
        int hi = h + HN; if (hi >= NN) hi -= NN;
        float2 cv = csm[(c*NN + hi)*NN + wi];
        float2 pv = pin[(s*NN + hi)*NN + wi];
        Ash[k][tid] = cml(cv, pv);
    }
    __syncthreads();
    fft320<1>(Ash[lane], Bsh[lane], Wsh, u);
    int wo = tid + HN; if (wo >= NN) wo -= NN;
    #pragma unroll
    for (int k = 0; k < 4; k++)
        d_scr[(g*NN + h0 + k)*NN + wo] = Ash[k][tid];
}

// ---------------- K2: fused column fwd FFT + mask (+scale) + column inv FFT ----------------
__global__ void __launch_bounds__(320) k_col_ata(const float* __restrict__ mask, float mscale){
    __shared__ float2 Ash[4][321], Bsh[4][321], Wsh[NN];
    __shared__ float  Msh[4][320];
    int tid = threadIdx.x, lane = tid / 80, u = tid % 80;
    Wsh[tid] = d_W[tid];
    int bid = blockIdx.x;
    int g = bid / 80;
    int cw0 = (bid % 80) * 4;
    int s = g >> 4;
    int cc = tid & 3, hh = tid >> 2;
    #pragma unroll
    for (int k = 0; k < 4; k++){
        int h = hh + 80*k;
        Ash[cc][h] = d_scr[(g*NN + h)*NN + cw0 + cc];
        int hr = h + HN; if (hr >= NN) hr -= NN;
        Msh[cc][h] = mask[(s*NN + hr)*NN + cw0 + cc] * mscale;
    }
    __syncthreads();
    fft320<1>(Ash[lane], Bsh[lane], Wsh, u);
    #pragma unroll
    for (int k = 0; k < 4; k++){
        int j = u + 80*k;
        float m = Msh[lane][j];
        float2 v = Ash[lane][j];
        Ash[lane][j] = make_float2(v.x*m, v.y*m);
    }
    __syncthreads();
    fft320<-1>(Ash[lane], Bsh[lane], Wsh, u);
    #pragma unroll
    for (int k = 0; k < 4; k++){
        int h = hh + 80*k;
        d_scr[(g*NN + h)*NN + cw0 + cc] = Ash[cc][h];
    }
}

// ---------------- K2b: RHS column inverse FFT of mask*kdata (ishift folded) ----------------
__global__ void __launch_bounds__(320) k_col_rhs(const float2* __restrict__ kd,
                                                 const float* __restrict__ mask, float mscale){
    __shared__ float2 Ash[4][321], Bsh[4][321], Wsh[NN];
    int tid = threadIdx.x, lane = tid / 80, u = tid % 80;
    Wsh[tid] = d_W[tid];
    int bid = blockIdx.x;
    int g = bid / 80;
    int cw0 = (bid % 80) * 4;
    int s = g >> 4;
    int cc = tid & 3, hh = tid >> 2;
    #pragma unroll
    for (int k = 0; k < 4; k++){
        int j = hh + 80*k;
        int hr = j + HN; if (hr >= NN) hr -= NN;
        float  m = mask[(s*NN + hr)*NN + cw0 + cc] * mscale;
        float2 v = kd[(g*NN + hr)*NN + cw0 + cc];
        Ash[cc][j] = make_float2(v.x*m, v.y*m);
    }
    __syncthreads();
    fft320<-1>(Ash[lane], Bsh[lane], Wsh, u);
    #pragma unroll
    for (int k = 0; k < 4; k++){
        int h = hh + 80*k;
        d_scr[(g*NN + h)*NN + cw0 + cc] = Ash[cc][h];
    }
}

// ---------------- K3: inverse row FFT + coil combine + rho*z + partial dot ----------------
__global__ void __launch_bounds__(320) k_inv_row(const float2* __restrict__ csm,
                                                 const float2* __restrict__ z,
                                                 float2* __restrict__ out,
                                                 float* __restrict__ part,
                                                 int dotMode){
    __shared__ float2 Ash[4][321], Bsh[4][321], Wsh[NN];
    int tid = threadIdx.x, lane = tid / 80, u = tid % 80;
    Wsh[tid] = d_W[tid];
    int bid = blockIdx.x;
    int s  = bid / NN;
    int hp = bid % NN;
    int hf = hp + HN; if (hf >= NN) hf -= NN;
    int wi = tid + HN; if (wi >= NN) wi -= NN;
    float2 acc = make_float2(0.f, 0.f);
    for (int it = 0; it < 4; ++it){
        __syncthreads();
        #pragma unroll
        for (int k = 0; k < 4; k++){
            int g = s*16 + (k + 4*it);
            Ash[k][tid] = d_scr[(g*NN + hp)*NN + wi];
        }
        __syncthreads();
        fft320<-1>(Ash[lane], Bsh[lane], Wsh, u);
        #pragma unroll
        for (int k = 0; k < 4; k++){
            int c = k + 4*it;
            float2 v  = Ash[k][wi];
            float2 sc = csm[(c*NN + hf)*NN + tid];
            acc = cad(acc, cmlcj(v, sc));
        }
    }
    int oi = (s*NN + hf)*NN + tid;
    float2 zv = z[oi];
    float2 o  = make_float2(fmaf(RHO_F, zv.x, acc.x), fmaf(RHO_F, zv.y, acc.y));
    out[oi] = o;
    float dv = dotMode ? (o.x*o.x + o.y*o.y) : (zv.x*o.x + zv.y*o.y);
    reduce320(dv, part);
}

// ---------------- CG vector updates (scalars computed in-block, no k_fin) ----------------
__global__ void __launch_bounds__(256) k_init_vec(float* __restrict__ pr0){
    int i = blockIdx.x*256 + threadIdx.x;
    d_x[i] = make_float2(0.f, 0.f);
    d_p[i] = d_r[i];
    if (threadIdx.x == 0 && blockIdx.x >= 1280) pr0[blockIdx.x] = 0.f;  // zero tail of init partials
}

// alpha = sum(curR)/(sum(partP)+eps); x += alpha p; if !last: r -= alpha Ap, nxtR[b]=|r|^2 partial
// if last: write x+alpha*p straight to out, skip r update.
__global__ void __launch_bounds__(256) k_axpy(const float* __restrict__ partP,
                                              const float* __restrict__ curR,
                                              float* __restrict__ nxtR,
                                              float2* __restrict__ outp,
                                              int last){
    float rs  = block_sum_arr(curR, 1600);
    float pAp = block_sum_arr(partP, 1280);
    float alpha = rs / (pAp + EPS_F);

    int i = blockIdx.x*256 + threadIdx.x;
    float2 pv = d_p[i];
    float2 xv = d_x[i];
    xv.x = fmaf(alpha, pv.x, xv.x); xv.y = fmaf(alpha, pv.y, xv.y);
    if (last){
        outp[i] = xv;
        return;
    }
    d_x[i] = xv;
    float2 av = d_Ap[i];
    float2 rv = d_r[i];
    rv.x = fmaf(-alpha, av.x, rv.x); rv.y = fmaf(-alpha, av.y, rv.y);
    d_r[i] = rv;
    float dv = rv.x*rv.x + rv.y*rv.y;
    __shared__ float rb[8];
    int tid = threadIdx.x;
    #pragma unroll
    for (int o = 16; o > 0; o >>= 1) dv += __shfl_down_sync(0xffffffffu, dv, o);
    if ((tid & 31) == 0) rb[tid >> 5] = dv;
    __syncthreads();
    if (tid == 0){
        float t = 0.f;
        #pragma unroll
        for (int k = 0; k < 8; k++) t += rb[k];
        nxtR[blockIdx.x] = t;
    }
}

// beta = sum(nxtR)/(sum(curR)+eps); p = r + beta p
__global__ void __launch_bounds__(256) k_updp(const float* __restrict__ curR,
                                              const float* __restrict__ nxtR){
    float rsn = block_sum_arr(nxtR, 1600);
    float rso = block_sum_arr(curR, 1600);
    float beta = rsn / (rso + EPS_F);
    int i = blockIdx.x*256 + threadIdx.x;
    float2 rv = d_r[i], pv = d_p[i];
    d_p[i] = make_float2(fmaf(beta, pv.x, rv.x), fmaf(beta, pv.y, rv.y));
}

// ---------------- launch ----------------
extern "C" void kernel_launch(void* const* d_in, const int* in_sizes, int n_in,
                              void* d_out, int out_size){
    const float2* kd = nullptr;
    const float2* I  = nullptr;
    const float2* csm = nullptr;
    const float*  mask = nullptr;
    for (int i = 0; i < n_in; i++){
        int sz = in_sizes[i];
        if      (sz == 13107200) kd   = (const float2*)d_in[i];
        else if (sz == 819200)   I    = (const float2*)d_in[i];
        else if (sz == 3276800)  csm  = (const float2*)d_in[i];
        else if (sz == 409600)   mask = (const float*) d_in[i];
    }

    float2 *rp, *pp, *App;
    float *partP, *pr0, *pr1;
    cudaGetSymbolAddress((void**)&rp,    d_r);
    cudaGetSymbolAddress((void**)&pp,    d_p);
    cudaGetSymbolAddress((void**)&App,   d_Ap);
    cudaGetSymbolAddress((void**)&partP, d_partP);
    cudaGetSymbolAddress((void**)&pr0,   d_pr0);
    cudaGetSymbolAddress((void**)&pr1,   d_pr1);

    const float invN  = 1.0f / 320.0f;            // ortho inverse (rhs)
    const float invN2 = 1.0f / (320.0f * 320.0f); // fwd*inv ortho (AtA)

    k_init_tw<<<1, 320>>>();

    // rhs = EH(kdata) + rho*I  -> r ; pr0 = |r0|^2 partials ; x = 0 ; p = r
    k_col_rhs<<<5120, 320>>>(kd, mask, invN);
    k_inv_row<<<1280, 320>>>(csm, I, rp, pr0, 1);
    k_init_vec<<<1600, 256>>>(pr0);

    for (int it = 0; it < 15; ++it){
        float* curR = (it & 1) ? pr1 : pr0;   // |r_it|^2 partials
        float* nxtR = (it & 1) ? pr0 : pr1;   // |r_{it+1}|^2 partials
        int last = (it == 14);

        k_fwd_row<<<5120, 320>>>(csm, pp);                    // scr = FFT_rows(csm*p)
        k_col_ata<<<5120, 320>>>(mask, invN2);                // scr = IFFT_cols(mask*FFT_cols(scr))
        k_inv_row<<<1280, 320>>>(csm, pp, App, partP, 0);     // Ap ; partP = p.Ap partials
        k_axpy<<<1600, 256>>>(partP, curR, nxtR,
                              (float2*)d_out, last);          // alpha in-block; x,r update
        if (!last)
            k_updp<<<1600, 256>>>(curR, nxtR);                // beta in-block; p = r + beta p
    }
    (void)out_size;
}

// round 4
// speedup vs baseline: 1.1029x; 1.1029x over previous
#include <cuda_runtime.h>
#include <math.h>

#define NN 320
#define HN 160
#define NPIX (NN*NN)
#define NVEC (4*NPIX)        // 409600 complex
#define NIMG 64              // 4 shots * 16 coils
#define RHO_F 0.1f
#define EPS_F 1e-12f

// ---------------- device globals (scratch) ----------------
__device__ float2 d_scr[NIMG*NPIX];   // 52.4 MB k-space / hybrid scratch
__device__ float2 d_x[NVEC];
__device__ float2 d_r[NVEC];
__device__ float2 d_p[NVEC];
__device__ float2 d_Ap[NVEC];
__device__ float2 d_W[NN];            // twiddle table exp(-2*pi*i*k/320)
__device__ float  d_partP[1280];      // pAp partials
__device__ float  d_pr[1600];         // |r|^2 partials
__device__ float  d_sc[4];            // 0: rs, 1: alpha, 2: beta

// ---------------- complex helpers ----------------
__device__ __forceinline__ float2 cad(float2 a, float2 b){ return make_float2(a.x+b.x, a.y+b.y); }
__device__ __forceinline__ float2 csb(float2 a, float2 b){ return make_float2(a.x-b.x, a.y-b.y); }
__device__ __forceinline__ float2 cml(float2 a, float2 b){
    return make_float2(fmaf(a.x,b.x,-a.y*b.y), fmaf(a.x,b.y, a.y*b.x));
}
__device__ __forceinline__ float2 cmlcj(float2 a, float2 b){ // a * conj(b)
    return make_float2(fmaf(a.x,b.x, a.y*b.y), fmaf(a.y,b.x,-a.x*b.y));
}

template<int DIR>
__device__ __forceinline__ float2 tw(const float2* W, int idx){
    float2 w = W[idx];
    return (DIR > 0) ? w : make_float2(w.x, -w.y);
}

// ---------------- Stockham radix-4 stage ----------------
template<int SS, int MM, int DIR>
__device__ __forceinline__ void stage_r4(const float2* src, float2* dst, const float2* W, int u){
    int p = u / SS;
    int q = u - p * SS;
    float2 a0 = src[q + SS*p];
    float2 a1 = src[q + SS*(p + MM)];
    float2 a2 = src[q + SS*(p + 2*MM)];
    float2 a3 = src[q + SS*(p + 3*MM)];
    float2 t0 = cad(a0,a2), t1 = csb(a0,a2), t2 = cad(a1,a3), t3 = csb(a1,a3);
    float2 b0 = cad(t0,t2), b2 = csb(t0,t2);
    float2 b1, b3;
    if (DIR > 0){
        b1 = make_float2(t1.x + t3.y, t1.y - t3.x);
        b3 = make_float2(t1.x - t3.y, t1.y + t3.x);
    } else {
        b1 = make_float2(t1.x - t3.y, t1.y + t3.x);
        b3 = make_float2(t1.x + t3.y, t1.y - t3.x);
    }
    int base = q + SS*4*p;
    dst[base]        = b0;
    dst[base +   SS] = cml(b1, tw<DIR>(W,     SS*p));
    dst[base + 2*SS] = cml(b2, tw<DIR>(W, 2 * SS*p));
    dst[base + 3*SS] = cml(b3, tw<DIR>(W, 3 * SS*p));
}

// ---------------- radix-5 first stage (used by both variants) ----------------
template<int DIR>
__device__ __forceinline__ void stage_r5(const float2* A, float2* B, const float2* W, int u){
    if (u < 64){
        float2 a0=A[u], a1=A[u+64], a2=A[u+128], a3=A[u+192], a4=A[u+256];
        const float C1 =  0.3090169943749474241f;
        const float C2 = -0.8090169943749474241f;
        const float S1 =  0.9510565162951535721f;
        const float S2 =  0.5877852522924731292f;
        float2 t1 = cad(a1,a4), t2 = cad(a2,a3), t3 = csb(a1,a4), t4 = csb(a2,a3);
        float2 b0 = make_float2(a0.x + t1.x + t2.x, a0.y + t1.y + t2.y);
        float2 m1 = make_float2(fmaf(C1,t1.x, fmaf(C2,t2.x, a0.x)),
                                fmaf(C1,t1.y, fmaf(C2,t2.y, a0.y)));
        float2 m2 = make_float2(fmaf(C2,t1.x, fmaf(C1,t2.x, a0.x)),
                                fmaf(C2,t1.y, fmaf(C1,t2.y, a0.y)));
        float2 w1 = make_float2(fmaf(S1,t3.x,  S2*t4.x), fmaf(S1,t3.y,  S2*t4.y));
        float2 w2 = make_float2(fmaf(S2,t3.x, -S1*t4.x), fmaf(S2,t3.y, -S1*t4.y));
        float2 b1,b2,b3,b4;
        if (DIR > 0){
            b1 = make_float2(m1.x + w1.y, m1.y - w1.x);
            b4 = make_float2(m1.x - w1.y, m1.y + w1.x);
            b2 = make_float2(m2.x + w2.y, m2.y - w2.x);
            b3 = make_float2(m2.x - w2.y, m2.y + w2.x);
        } else {
            b1 = make_float2(m1.x - w1.y, m1.y + w1.x);
            b4 = make_float2(m1.x + w1.y, m1.y - w1.x);
            b2 = make_float2(m2.x - w2.y, m2.y + w2.x);
            b3 = make_float2(m2.x + w2.y, m2.y - w2.x);
        }
        B[5*u]   = b0;
        B[5*u+1] = cml(b1, tw<DIR>(W,   u));
        B[5*u+2] = cml(b2, tw<DIR>(W, 2*u));
        B[5*u+3] = cml(b3, tw<DIR>(W, 3*u));
        B[5*u+4] = cml(b4, tw<DIR>(W, 4*u));
    }
}

// ---------------- full 320-pt FFT in shared (4 exchange stages) ----------------
template<int DIR>
__device__ __forceinline__ void fft320(float2* A, float2* B, const float2* W, int u){
    stage_r5<DIR>(A, B, W, u);       __syncthreads();
    stage_r4<5,16,DIR>(B, A, W, u);  __syncthreads();
    stage_r4<20,4,DIR>(A, B, W, u);  __syncthreads();
    stage_r4<80,1,DIR>(B, A, W, u);  __syncthreads();
}

// ---------------- first 3 stages only; results left in B (pre-final) ----------------
template<int DIR>
__device__ __forceinline__ void fft320_pre(float2* A, float2* B, const float2* W, int u){
    stage_r5<DIR>(A, B, W, u);       __syncthreads();
    stage_r4<5,16,DIR>(B, A, W, u);  __syncthreads();
    stage_r4<20,4,DIR>(A, B, W, u);  __syncthreads();
}

// ---------------- final radix-4 (unit twiddles) in registers ----------------
// o[r] corresponds to position u + 80*r.
template<int DIR>
__device__ __forceinline__ void final_r4(const float2* B, int u, float2 o[4]){
    float2 a0 = B[u], a1 = B[u+80], a2 = B[u+160], a3 = B[u+240];
    float2 t0 = cad(a0,a2), t1 = csb(a0,a2), t2 = cad(a1,a3), t3 = csb(a1,a3);
    o[0] = cad(t0,t2);
    o[2] = csb(t0,t2);
    if (DIR > 0){
        o[1] = make_float2(t1.x + t3.y, t1.y - t3.x);
        o[3] = make_float2(t1.x - t3.y, t1.y + t3.x);
    } else {
        o[1] = make_float2(t1.x - t3.y, t1.y + t3.x);
        o[3] = make_float2(t1.x + t3.y, t1.y - t3.x);
    }
}

__device__ __forceinline__ int rot160(int j){ return (j < HN) ? j + HN : j - HN; }

// ---------------- 320-thread block reduce -> part[bid] ----------------
__device__ __forceinline__ void reduce320(float v, float* part){
    __shared__ float rb[10];
    int tid = threadIdx.x;
    #pragma unroll
    for (int o = 16; o > 0; o >>= 1) v += __shfl_down_sync(0xffffffffu, v, o);
    if ((tid & 31) == 0) rb[tid >> 5] = v;
    __syncthreads();
    if (tid == 0){
        float t = 0.f;
        #pragma unroll
        for (int i = 0; i < 10; i++) t += rb[i];
        part[blockIdx.x] = t;
    }
}

// ---------------- init: twiddles ----------------
__global__ void k_init_tw(){
    int k = threadIdx.x;
    double a = -2.0 * 3.14159265358979323846 * (double)k / 320.0;
    d_W[k] = make_float2((float)cos(a), (float)sin(a));
}

// ---------------- K1: forward row FFT of csm*p, ishift folded, fused final stage ----------------
__global__ void __launch_bounds__(320) k_fwd_row(const float2* __restrict__ csm,
                                                 const float2* __restrict__ pin){
    __shared__ float2 Ash[4][321], Bsh[4][321], Wsh[NN];
    int tid = threadIdx.x, lane = tid / 80, u = tid % 80;
    Wsh[tid] = d_W[tid];
    int bid = blockIdx.x;
    int g  = bid / 80;            // s*16 + c
    int h0 = (bid % 80) * 4;
    int s = g >> 4, c = g & 15;
    int wi = rot160(tid);
    #pragma unroll
    for (int k = 0; k < 4; k++){
        int hi = rot160(h0 + k);
        float2 cv = csm[(c*NN + hi)*NN + wi];
        float2 pv = pin[(s*NN + hi)*NN + wi];
        Ash[k][tid] = cml(cv, pv);
    }
    __syncthreads();
    fft320_pre<1>(Ash[lane], Bsh[lane], Wsh, u);
    float2 o[4];
    final_r4<1>(Bsh[lane], u, o);
    int h = h0 + lane;
    long base = (long)(g*NN + h)*NN;
    #pragma unroll
    for (int r = 0; r < 4; r++)
        d_scr[base + rot160(u + 80*r)] = o[r];
}

// ---------------- K2: fused column fwd FFT + mask (regs) + column inv FFT ----------------
__global__ void __launch_bounds__(320) k_col_ata(const float* __restrict__ mask, float mscale){
    __shared__ float2 Ash[4][321], Bsh[4][321], Wsh[NN];
    __shared__ float  Msh[4][320];
    int tid = threadIdx.x, lane = tid / 80, u = tid % 80;
    Wsh[tid] = d_W[tid];
    int bid = blockIdx.x;
    int g = bid / 80;
    int cw0 = (bid % 80) * 4;
    int s = g >> 4;
    int e = tid & 1, hh = tid >> 1;       // float4 IO mapping: 2 rows per thread
    // mask: one float4 row per thread
    {
        int hr = rot160(tid);
        const float4* m4 = (const float4*)(mask + (s*NN + hr)*NN + cw0);
        float4 m = m4[0];
        Msh[0][tid] = m.x*mscale; Msh[1][tid] = m.y*mscale;
        Msh[2][tid] = m.z*mscale; Msh[3][tid] = m.w*mscale;
    }
    #pragma unroll
    for (int rr = 0; rr < 2; rr++){
        int h = hh + 160*rr;
        const float4* s4 = (const float4*)&d_scr[(long)(g*NN + h)*NN + cw0 + 2*e];
        float4 v = s4[0];
        Ash[2*e  ][h] = make_float2(v.x, v.y);
        Ash[2*e+1][h] = make_float2(v.z, v.w);
    }
    __syncthreads();
    fft320_pre<1>(Ash[lane], Bsh[lane], Wsh, u);
    float2 o[4];
    final_r4<1>(Bsh[lane], u, o);
    // mask in registers, write back at natural positions for the inverse FFT
    #pragma unroll
    for (int r = 0; r < 4; r++){
        int j = u + 80*r;
        float m = Msh[lane][j];
        Ash[lane][j] = make_float2(o[r].x*m, o[r].y*m);
    }
    __syncthreads();
    fft320_pre<-1>(Ash[lane], Bsh[lane], Wsh, u);
    final_r4<-1>(Bsh[lane], u, o);
    #pragma unroll
    for (int r = 0; r < 4; r++)
        Ash[lane][u + 80*r] = o[r];
    __syncthreads();
    #pragma unroll
    for (int rr = 0; rr < 2; rr++){
        int h = hh + 160*rr;
        float4* s4 = (float4*)&d_scr[(long)(g*NN + h)*NN + cw0 + 2*e];
        float2 v0 = Ash[2*e][h], v1 = Ash[2*e+1][h];
        s4[0] = make_float4(v0.x, v0.y, v1.x, v1.y);
    }
}

// ---------------- K2b: RHS column inverse FFT of mask*kdata (ishift folded) ----------------
__global__ void __launch_bounds__(320) k_col_rhs(const float2* __restrict__ kd,
                                                 const float* __restrict__ mask, float mscale){
    __shared__ float2 Ash[4][321], Bsh[4][321], Wsh[NN];
    int tid = threadIdx.x, lane = tid / 80, u = tid % 80;
    Wsh[tid] = d_W[tid];
    int bid = blockIdx.x;
    int g = bid / 80;
    int cw0 = (bid % 80) * 4;
    int s = g >> 4;
    int e = tid & 1, hh = tid >> 1;
    #pragma unroll
    for (int rr = 0; rr < 2; rr++){
        int j = hh + 160*rr;
        int hr = rot160(j);
        const float4* k4 = (const float4*)&kd[(long)(g*NN + hr)*NN + cw0 + 2*e];
        float4 v = k4[0];
        float m0 = mask[(s*NN + hr)*NN + cw0 + 2*e    ] * mscale;
        float m1 = mask[(s*NN + hr)*NN + cw0 + 2*e + 1] * mscale;
        Ash[2*e  ][j] = make_float2(v.x*m0, v.y*m0);
        Ash[2*e+1][j] = make_float2(v.z*m1, v.w*m1);
    }
    __syncthreads();
    fft320<-1>(Ash[lane], Bsh[lane], Wsh, u);
    #pragma unroll
    for (int rr = 0; rr < 2; rr++){
        int h = hh + 160*rr;
        float4* s4 = (float4*)&d_scr[(long)(g*NN + h)*NN + cw0 + 2*e];
        float2 v0 = Ash[2*e][h], v1 = Ash[2*e+1][h];
        s4[0] = make_float4(v0.x, v0.y, v1.x, v1.y);
    }
}

// ---------------- K3: inverse row FFT + coil combine + rho*z + partial dot ----------------
// initMode: also write p = out and x = 0 (used for the RHS pass)
__global__ void __launch_bounds__(320) k_inv_row(const float2* __restrict__ csm,
                                                 const float2* __restrict__ z,
                                                 float2* __restrict__ out,
                                                 float* __restrict__ part,
                                                 int dotMode, int initMode){
    __shared__ float2 Ash[4][321], Bsh[4][321], Wsh[NN];
    int tid = threadIdx.x, lane = tid / 80, u = tid % 80;
    Wsh[tid] = d_W[tid];
    int bid = blockIdx.x;
    int s  = bid / NN;
    int hp = bid % NN;
    int hf = rot160(hp);
    int wi = rot160(tid);
    float2 acc = make_float2(0.f, 0.f);
    for (int it = 0; it < 4; ++it){
        __syncthreads();
        #pragma unroll
        for (int k = 0; k < 4; k++){
            int g = s*16 + (k + 4*it);
            Ash[k][tid] = d_scr[(long)(g*NN + hp)*NN + wi];
        }
        __syncthreads();
        fft320<-1>(Ash[lane], Bsh[lane], Wsh, u);
        #pragma unroll
        for (int k = 0; k < 4; k++){
            int c = k + 4*it;
            float2 v  = Ash[k][wi];
            float2 sc = csm[(c*NN + hf)*NN + tid];
            acc = cad(acc, cmlcj(v, sc));
        }
    }
    int oi = (s*NN + hf)*NN + tid;
    float2 zv = z[oi];
    float2 o  = make_float2(fmaf(RHO_F, zv.x, acc.x), fmaf(RHO_F, zv.y, acc.y));
    out[oi] = o;
    if (initMode){
        d_p[oi] = o;
        d_x[oi] = make_float2(0.f, 0.f);
    }
    float dv = dotMode ? (o.x*o.x + o.y*o.y) : (zv.x*o.x + zv.y*o.y);
    reduce320(dv, part);
}

// ---------------- scalar finalize (single block) ----------------
// mode 0 (alpha): if nRs>0: rs = sum(rsArr[0:nRs]) -> d_sc[0]; alpha = d_sc[0]/(sum(pApArr)+eps)
// mode 1 (beta):  t = sum(rsArr); beta = t/(d_sc[0]+eps); d_sc[0] = t
__global__ void __launch_bounds__(1024) k_fin(const float* __restrict__ arrA, int nA,
                                              const float* __restrict__ arrB, int nB,
                                              int mode){
    __shared__ float sb[1024];
    int tid = threadIdx.x;
    float v = 0.f;
    for (int i = tid; i < nA; i += 1024) v += arrA[i];
    sb[tid] = v; __syncthreads();
    #pragma unroll
    for (int st = 512; st > 0; st >>= 1){
        if (tid < st) sb[tid] += sb[tid + st];
        __syncthreads();
    }
    float sumA = sb[0];
    __syncthreads();
    float w = 0.f;
    if (nB > 0){
        for (int i = tid; i < nB; i += 1024) w += arrB[i];
    }
    sb[tid] = w; __syncthreads();
    #pragma unroll
    for (int st = 512; st > 0; st >>= 1){
        if (tid < st) sb[tid] += sb[tid + st];
        __syncthreads();
    }
    if (tid == 0){
        float sumB = sb[0];
        if (mode == 0){
            float rs = (nB > 0) ? sumB : d_sc[0];   // arrB = rs partials (iter 0 only)
            if (nB > 0) d_sc[0] = rs;
            d_sc[1] = rs / (sumA + EPS_F);          // arrA = pAp partials
        } else {
            d_sc[2] = sumA / (d_sc[0] + EPS_F);     // arrA = new rs partials
            d_sc[0] = sumA;
        }
    }
}

// ---------------- CG vector updates ----------------
__global__ void __launch_bounds__(256) k_axpy(float* __restrict__ part,
                                              float2* __restrict__ outp, int last){
    int i = blockIdx.x*256 + threadIdx.x;
    float alpha = d_sc[1];
    float2 pv = d_p[i];
    float2 xv = d_x[i];
    xv.x = fmaf(alpha, pv.x, xv.x); xv.y = fmaf(alpha, pv.y, xv.y);
    if (last){
        outp[i] = xv;
        return;
    }
    d_x[i] = xv;
    float2 av = d_Ap[i];
    float2 rv = d_r[i];
    rv.x = fmaf(-alpha, av.x, rv.x); rv.y = fmaf(-alpha, av.y, rv.y);
    d_r[i] = rv;
    float dv = rv.x*rv.x + rv.y*rv.y;
    __shared__ float rb[8];
    int tid = threadIdx.x;
    #pragma unroll
    for (int o = 16; o > 0; o >>= 1) dv += __shfl_down_sync(0xffffffffu, dv, o);
    if ((tid & 31) == 0) rb[tid >> 5] = dv;
    __syncthreads();
    if (tid == 0){
        float t = 0.f;
        #pragma unroll
        for (int k = 0; k < 8; k++) t += rb[k];
        part[blockIdx.x] = t;
    }
}
__global__ void __launch_bounds__(256) k_updp(){
    int i = blockIdx.x*256 + threadIdx.x;
    float beta = d_sc[2];
    float2 rv = d_r[i], pv = d_p[i];
    d_p[i] = make_float2(fmaf(beta, pv.x, rv.x), fmaf(beta, pv.y, rv.y));
}

// ---------------- launch ----------------
extern "C" void kernel_launch(void* const* d_in, const int* in_sizes, int n_in,
                              void* d_out, int out_size){
    const float2* kd = nullptr;
    const float2* I  = nullptr;
    const float2* csm = nullptr;
    const float*  mask = nullptr;
    for (int i = 0; i < n_in; i++){
        int sz = in_sizes[i];
        if      (sz == 13107200) kd   = (const float2*)d_in[i];
        else if (sz == 819200)   I    = (const float2*)d_in[i];
        else if (sz == 3276800)  csm  = (const float2*)d_in[i];
        else if (sz == 409600)   mask = (const float*) d_in[i];
    }

    float2 *rp, *pp, *App;
    float *partP, *pr;
    cudaGetSymbolAddress((void**)&rp,    d_r);
    cudaGetSymbolAddress((void**)&pp,    d_p);
    cudaGetSymbolAddress((void**)&App,   d_Ap);
    cudaGetSymbolAddress((void**)&partP, d_partP);
    cudaGetSymbolAddress((void**)&pr,    d_pr);

    const float invN  = 1.0f / 320.0f;            // ortho inverse (rhs)
    const float invN2 = 1.0f / (320.0f * 320.0f); // fwd*inv ortho (AtA)

    k_init_tw<<<1, 320>>>();                                   // #1

    // rhs = EH(kdata) + rho*I -> r ; pr[0:1280] = |r0|^2 partials ; p=r ; x=0
    k_col_rhs<<<5120, 320>>>(kd, mask, invN);                  // #2
    k_inv_row<<<1280, 320>>>(csm, I, rp, pr, 1, 1);            // #3

    for (int it = 0; it < 15; ++it){
        int last = (it == 14);
        k_fwd_row<<<5120, 320>>>(csm, pp);                     // #4 on iter 0 (profiled)
        k_col_ata<<<5120, 320>>>(mask, invN2);
        k_inv_row<<<1280, 320>>>(csm, pp, App, partP, 0, 0);
        // alpha (iter 0 also folds rs0 = sum of pr[0:1280])
        k_fin<<<1, 1024>>>(partP, 1280, pr, (it == 0) ? 1280 : 0, 0);
        k_axpy<<<1600, 256>>>(pr, (float2*)d_out, last);
        if (!last){
            k_fin<<<1, 1024>>>(pr, 1600, pr, 0, 1);            // beta
            k_updp<<<1600, 256>>>();
        }
    }
    (void)out_size;
}